// round 1
// baseline (speedup 1.0000x reference)
#include <cuda_runtime.h>

#define NA 50000
#define NM 50000
#define NI 600000
#define NG 512
#define H 64
#define MD 94
#define HOUT 128
#define ZK 158          // hx (64) + motif_attr (94)
#define BN_EPS 1e-5f

// ---------------- device scratch (no allocs allowed) ----------------
__device__ float d_x[NA * H];      // atom embeddings
__device__ float d_hx[NM * H];     // hyperedge sum (then mean on the fly)
__device__ float d_cnt_h[NM];      // incidence count per motif
__device__ float d_cnt_s[NA];      // incidence count per atom
__device__ float d_Af[NA * H];     // x @ w_f[0:64]
__device__ float d_Ac[NA * H];     // x @ w_c[0:64]
__device__ float d_Mf[NM * H];     // [hx|attr] @ w_f[64:222] + b_f
__device__ float d_Mc[NM * H];     // [hx|attr] @ w_c[64:222] + b_c
__device__ float d_osum[NA * H];   // scattered message sum per atom
__device__ float d_bnsum[H];
__device__ float d_bnsq[H];
__device__ float d_gsum[NG * H];
__device__ float d_gcnt[NG];

// ---------------- fast math helpers ----------------
__device__ __forceinline__ float ex2f(float x) { float r; asm("ex2.approx.ftz.f32 %0,%1;" : "=f"(r) : "f"(x)); return r; }
__device__ __forceinline__ float lg2f(float x) { float r; asm("lg2.approx.ftz.f32 %0,%1;" : "=f"(r) : "f"(x)); return r; }
__device__ __forceinline__ float rcpf(float x) { float r; asm("rcp.approx.ftz.f32 %0,%1;" : "=f"(r) : "f"(x)); return r; }

#define L2E 1.4426950408889634f
#define LN2 0.6931471805599453f

__device__ __forceinline__ float gatef(float a, float b) {
    // sigmoid(a) * softplus(b)
    float sg = rcpf(1.0f + ex2f(-a * L2E));
    float sp = lg2f(1.0f + ex2f(b * L2E)) * LN2;
    return sg * sp;
}

__device__ __forceinline__ void red_add_v4(float* p, float4 v) {
    asm volatile("red.global.add.v4.f32 [%0], {%1,%2,%3,%4};"
                 :: "l"(p), "f"(v.x), "f"(v.y), "f"(v.z), "f"(v.w) : "memory");
}

// ---------------- kernels ----------------
__global__ void k_zero() {
    int tid = blockIdx.x * blockDim.x + threadIdx.x;
    int stride = gridDim.x * blockDim.x;
    for (int i = tid; i < NM * H; i += stride) d_hx[i] = 0.f;
    for (int i = tid; i < NA * H; i += stride) d_osum[i] = 0.f;
    for (int i = tid; i < NM; i += stride) d_cnt_h[i] = 0.f;
    for (int i = tid; i < NA; i += stride) d_cnt_s[i] = 0.f;
    for (int i = tid; i < NG * H; i += stride) d_gsum[i] = 0.f;
    if (tid < NG) d_gcnt[tid] = 0.f;
    if (tid < H) { d_bnsum[tid] = 0.f; d_bnsq[tid] = 0.f; }
}

__global__ void k_embed(const int* __restrict__ az, const float* __restrict__ emb,
                        const int* __restrict__ batch) {
    int tid = blockIdx.x * blockDim.x + threadIdx.x;
    if (tid < NA * H) {
        int i = tid >> 6, f = tid & 63;
        d_x[tid] = emb[az[i] * H + f];
    }
    if (tid < NA) atomicAdd(&d_gcnt[batch[tid]], 1.0f);
}

__global__ void k_counts(const int* __restrict__ src, const int* __restrict__ hid) {
    int e = blockIdx.x * blockDim.x + threadIdx.x;
    if (e < NI) {
        atomicAdd(&d_cnt_s[src[e]], 1.0f);
        atomicAdd(&d_cnt_h[hid[e]], 1.0f);
    }
}

// phase A: scatter x[src] into hx[hid]  (16 threads / incidence, float4 lanes)
__global__ void k_scatter_hx(const int* __restrict__ src, const int* __restrict__ hid) {
    int tid = blockIdx.x * blockDim.x + threadIdx.x;
    if (tid >= NI * 16) return;
    int e = tid >> 4;
    int q = (tid & 15) << 2;
    int s = __ldg(src + e);
    int m = __ldg(hid + e);
    float4 v = *reinterpret_cast<const float4*>(d_x + s * H + q);
    red_add_v4(d_hx + m * H + q, v);
}

// per-atom GEMM:  [Af|Ac] = x @ [w_f[:64] | w_c[:64]]   (NA x 64) @ (64 x 128)
__global__ __launch_bounds__(256) void k_gemm_atoms(const float* __restrict__ w_f,
                                                    const float* __restrict__ w_c) {
    __shared__ float Wsm[64 * 128];
    __shared__ float Xsm[32 * 64];
    int t = threadIdx.x;
    int tx = t & 127, ty = t >> 7;

    for (int idx = t; idx < 64 * 128; idx += 256) {
        int k = idx >> 7, j = idx & 127;
        Wsm[idx] = (j < 64) ? w_f[k * H + j] : w_c[k * H + j - 64];
    }
    int row0 = blockIdx.x * 32;
    for (int idx = t; idx < 32 * 64; idx += 256) {
        int r = idx >> 6;
        int row = row0 + r;
        Xsm[idx] = (row < NA) ? d_x[row * H + (idx & 63)] : 0.f;
    }
    __syncthreads();

    float acc[16];
#pragma unroll
    for (int r = 0; r < 16; r++) acc[r] = 0.f;
#pragma unroll 8
    for (int k = 0; k < 64; k++) {
        float wv = Wsm[k * 128 + tx];
#pragma unroll
        for (int r = 0; r < 16; r++)
            acc[r] = fmaf(Xsm[(ty * 16 + r) * 64 + k], wv, acc[r]);
    }
#pragma unroll
    for (int r = 0; r < 16; r++) {
        int row = row0 + ty * 16 + r;
        if (row < NA) {
            if (tx < 64) d_Af[row * H + tx] = acc[r];
            else         d_Ac[row * H + (tx - 64)] = acc[r];
        }
    }
}

// per-motif GEMM:  [Mf|Mc] = [hx_mean | attr] @ [w_f[64:] | w_c[64:]] + [b_f|b_c]
__global__ __launch_bounds__(256) void k_gemm_motifs(const float* __restrict__ w_f,
                                                     const float* __restrict__ w_c,
                                                     const float* __restrict__ b_f,
                                                     const float* __restrict__ b_c,
                                                     const float* __restrict__ attr) {
    extern __shared__ float smbuf[];
    float* Wsm = smbuf;              // ZK * 128
    float* Xsm = smbuf + ZK * 128;   // 32 * ZK
    int t = threadIdx.x;
    int tx = t & 127, ty = t >> 7;

    for (int idx = t; idx < ZK * 128; idx += 256) {
        int k = idx >> 7, j = idx & 127;
        Wsm[idx] = (j < 64) ? w_f[(64 + k) * H + j] : w_c[(64 + k) * H + j - 64];
    }
    int row0 = blockIdx.x * 32;
    for (int idx = t; idx < 32 * ZK; idx += 256) {
        int r = idx / ZK;
        int k = idx - r * ZK;
        int row = row0 + r;
        float v = 0.f;
        if (row < NM) {
            if (k < 64) v = d_hx[row * H + k] * __fdividef(1.0f, fmaxf(d_cnt_h[row], 1.0f));
            else        v = attr[row * MD + (k - 64)];
        }
        Xsm[idx] = v;
    }
    __syncthreads();

    float acc[16];
#pragma unroll
    for (int r = 0; r < 16; r++) acc[r] = 0.f;
#pragma unroll 2
    for (int k = 0; k < ZK; k++) {
        float wv = Wsm[k * 128 + tx];
#pragma unroll
        for (int r = 0; r < 16; r++)
            acc[r] = fmaf(Xsm[(ty * 16 + r) * ZK + k], wv, acc[r]);
    }
#pragma unroll
    for (int r = 0; r < 16; r++) {
        int row = row0 + ty * 16 + r;
        if (row < NM) {
            if (tx < 64) d_Mf[row * H + tx] = acc[r] + b_f[tx];
            else         d_Mc[row * H + (tx - 64)] = acc[r] + b_c[tx - 64];
        }
    }
}

// phase B: per-incidence gated message + scatter to atoms
__global__ void k_msg(const int* __restrict__ src, const int* __restrict__ hid) {
    int tid = blockIdx.x * blockDim.x + threadIdx.x;
    if (tid >= NI * 16) return;
    int e = tid >> 4;
    int q = (tid & 15) << 2;
    int s = __ldg(src + e);
    int m = __ldg(hid + e);
    float4 af = *reinterpret_cast<const float4*>(d_Af + s * H + q);
    float4 mf = *reinterpret_cast<const float4*>(d_Mf + m * H + q);
    float4 ac = *reinterpret_cast<const float4*>(d_Ac + s * H + q);
    float4 mc = *reinterpret_cast<const float4*>(d_Mc + m * H + q);
    float4 r;
    r.x = gatef(af.x + mf.x, ac.x + mc.x);
    r.y = gatef(af.y + mf.y, ac.y + mc.y);
    r.z = gatef(af.z + mf.z, ac.z + mc.z);
    r.w = gatef(af.w + mf.w, ac.w + mc.w);
    red_add_v4(d_osum + s * H + q, r);
}

// BN statistics: per-feature sum & sumsq of out = osum / max(cnt,1)
__global__ void k_bnstats() {
    __shared__ float s1[256], s2[256];
    int t = threadIdx.x;
    float ls = 0.f, lq = 0.f;
    int stride = gridDim.x * blockDim.x;   // multiple of 64, so (i & 63) stays == (t & 63)
    for (int i = blockIdx.x * blockDim.x + t; i < NA * H; i += stride) {
        int row = i >> 6;
        float o = d_osum[i] * __fdividef(1.0f, fmaxf(d_cnt_s[row], 1.0f));
        ls += o;
        lq += o * o;
    }
    s1[t] = ls; s2[t] = lq;
    __syncthreads();
    if (t < 64) {
        float a = s1[t] + s1[t + 64] + s1[t + 128] + s1[t + 192];
        float b = s2[t] + s2[t + 64] + s2[t + 128] + s2[t + 192];
        atomicAdd(&d_bnsum[t], a);
        atomicAdd(&d_bnsq[t], b);
    }
}

// normalize + residual + relu + pool into graphs
__global__ void k_final(const int* __restrict__ batch, const float* __restrict__ gamma,
                        const float* __restrict__ beta) {
    int tid = blockIdx.x * blockDim.x + threadIdx.x;
    if (tid >= NA * 16) return;
    int i = tid >> 4;
    int q = (tid & 15) << 2;
    float rc = __fdividef(1.0f, fmaxf(d_cnt_s[i], 1.0f));
    float4 o = *reinterpret_cast<const float4*>(d_osum + i * H + q);
    float4 xv = *reinterpret_cast<const float4*>(d_x + i * H + q);
    float4 r;
    float ov[4] = {o.x, o.y, o.z, o.w};
    float xr[4] = {xv.x, xv.y, xv.z, xv.w};
    float res[4];
#pragma unroll
    for (int c = 0; c < 4; c++) {
        int f = q + c;
        float mu = d_bnsum[f] * (1.0f / NA);
        float var = d_bnsq[f] * (1.0f / NA) - mu * mu;
        float inv = rsqrtf(var + BN_EPS);
        float v = (ov[c] * rc - mu) * inv * gamma[f] + beta[f] + xr[c];
        res[c] = fmaxf(v, 0.f);
    }
    r.x = res[0]; r.y = res[1]; r.z = res[2]; r.w = res[3];
    int g = __ldg(batch + i);
    red_add_v4(d_gsum + g * H + q, r);
}

// MLP head: one block per graph
__global__ __launch_bounds__(128) void k_head(const float* __restrict__ w_l1,
                                              const float* __restrict__ b_l1,
                                              const float* __restrict__ w_out,
                                              const float* __restrict__ b_out,
                                              float* __restrict__ out) {
    __shared__ float gsm[64];
    __shared__ float red[128];
    int g = blockIdx.x;
    int t = threadIdx.x;
    if (t < 64) gsm[t] = d_gsum[g * H + t] * __fdividef(1.0f, fmaxf(d_gcnt[g], 1.0f));
    __syncthreads();
    float acc = b_l1[t];
#pragma unroll
    for (int f = 0; f < 64; f++)
        acc = fmaf(gsm[f], w_l1[f * HOUT + t], acc);
    float sp = lg2f(1.0f + ex2f(acc * L2E)) * LN2;  // softplus
    red[t] = sp * w_out[t];
    __syncthreads();
    if (t < 64) red[t] += red[t + 64];
    __syncthreads();
    if (t < 32) {
        float s = red[t] + red[t + 32];
#pragma unroll
        for (int off = 16; off > 0; off >>= 1)
            s += __shfl_down_sync(0xffffffff, s, off);
        if (t == 0) out[g] = s + b_out[0];
    }
}

// ---------------- launch ----------------
extern "C" void kernel_launch(void* const* d_in, const int* in_sizes, int n_in,
                              void* d_out, int out_size) {
    const int*   atom_z = (const int*)d_in[0];
    const float* attr   = (const float*)d_in[1];
    const int*   hei    = (const int*)d_in[2];
    const int*   batch  = (const int*)d_in[3];
    const float* emb    = (const float*)d_in[4];
    const float* w_f    = (const float*)d_in[5];
    const float* b_f    = (const float*)d_in[6];
    const float* w_c    = (const float*)d_in[7];
    const float* b_c    = (const float*)d_in[8];
    const float* gamma  = (const float*)d_in[9];
    const float* beta   = (const float*)d_in[10];
    const float* w_l1   = (const float*)d_in[11];
    const float* b_l1   = (const float*)d_in[12];
    const float* w_out  = (const float*)d_in[13];
    const float* b_out  = (const float*)d_in[14];
    float* out = (float*)d_out;

    const int* src = hei;         // hyperedge_index[0]
    const int* hid = hei + NI;    // hyperedge_index[1]

    const int dyn_smem = (ZK * 128 + 32 * ZK) * (int)sizeof(float);  // 101120 B
    cudaFuncSetAttribute(k_gemm_motifs, cudaFuncAttributeMaxDynamicSharedMemorySize, dyn_smem);

    k_zero<<<1024, 256>>>();
    k_embed<<<(NA * H + 255) / 256, 256>>>(atom_z, emb, batch);
    k_counts<<<(NI + 255) / 256, 256>>>(src, hid);
    k_scatter_hx<<<(NI * 16 + 255) / 256, 256>>>(src, hid);
    k_gemm_atoms<<<(NA + 31) / 32, 256>>>(w_f, w_c);
    k_gemm_motifs<<<(NM + 31) / 32, 256, dyn_smem>>>(w_f, w_c, b_f, b_c, attr);
    k_msg<<<(NI * 16 + 255) / 256, 256>>>(src, hid);
    k_bnstats<<<1024, 256>>>();
    k_final<<<(NA * 16 + 255) / 256, 256>>>(batch, gamma, beta);
    k_head<<<NG, 128>>>(w_l1, b_l1, w_out, b_out, out);
}

// round 2
// speedup vs baseline: 1.3365x; 1.3365x over previous
#include <cuda_runtime.h>

#define NA 50000
#define NM 50000
#define NI 600000
#define NG 512
#define H 64
#define MD 94
#define HOUT 128
#define ZK 158          // hx (64) + motif_attr (94)
#define NZ 101          // distinct atom types
#define BN_EPS 1e-5f

// ---------------- device scratch ----------------
__device__ float d_hx[NM * H];     // hyperedge sum
__device__ float d_cnt_h[NM];
__device__ float d_cnt_s[NA];
__device__ float d_Tf[NZ * H];     // emb @ w_f[:64]  (101-row table)
__device__ float d_Tc[NZ * H];     // emb @ w_c[:64]
__device__ float d_Mf[NM * H];
__device__ float d_Mc[NM * H];
__device__ float d_osum[NA * H];
__device__ float d_bnsum[H];
__device__ float d_bnsq[H];
__device__ float d_gsum[NG * H];
__device__ float d_gcnt[NG];

// ---------------- fast math ----------------
__device__ __forceinline__ float ex2f(float x) { float r; asm("ex2.approx.ftz.f32 %0,%1;" : "=f"(r) : "f"(x)); return r; }
__device__ __forceinline__ float lg2f(float x) { float r; asm("lg2.approx.ftz.f32 %0,%1;" : "=f"(r) : "f"(x)); return r; }
__device__ __forceinline__ float rcpf(float x) { float r; asm("rcp.approx.ftz.f32 %0,%1;" : "=f"(r) : "f"(x)); return r; }

#define L2E 1.4426950408889634f
#define LN2 0.6931471805599453f

__device__ __forceinline__ float gatef(float a, float b) {
    float sg = rcpf(1.0f + ex2f(-a * L2E));
    float sp = lg2f(1.0f + ex2f(b * L2E)) * LN2;
    return sg * sp;
}

__device__ __forceinline__ void red_add_v4(float* p, float4 v) {
    asm volatile("red.global.add.v4.f32 [%0], {%1,%2,%3,%4};"
                 :: "l"(p), "f"(v.x), "f"(v.y), "f"(v.z), "f"(v.w) : "memory");
}
__device__ __forceinline__ void red_add_1(float* p, float v) {
    asm volatile("red.global.add.f32 [%0], %1;" :: "l"(p), "f"(v) : "memory");
}

// ---------------- kernels ----------------
__global__ void k_zero() {
    int tid = blockIdx.x * blockDim.x + threadIdx.x;
    int stride = gridDim.x * blockDim.x;
    for (int i = tid; i < NM * H; i += stride) d_hx[i] = 0.f;
    for (int i = tid; i < NA * H; i += stride) d_osum[i] = 0.f;
    for (int i = tid; i < NM; i += stride) d_cnt_h[i] = 0.f;
    for (int i = tid; i < NA; i += stride) d_cnt_s[i] = 0.f;
    for (int i = tid; i < NG * H; i += stride) d_gsum[i] = 0.f;
    if (tid < NG) d_gcnt[tid] = 0.f;
    if (tid < H) { d_bnsum[tid] = 0.f; d_bnsq[tid] = 0.f; }
}

// per-atom-TYPE table GEMM: Tf/Tc = emb @ [w_f[:64] | w_c[:64]]  (101x64x128)
__global__ __launch_bounds__(128) void k_tables(const float* __restrict__ emb,
                                                const float* __restrict__ w_f,
                                                const float* __restrict__ w_c) {
    __shared__ float e[H];
    int z = blockIdx.x;
    int tx = threadIdx.x;
    if (tx < H) e[tx] = emb[z * H + tx];
    __syncthreads();
    float acc = 0.f;
    if (tx < 64) {
#pragma unroll 8
        for (int k = 0; k < H; k++) acc = fmaf(e[k], w_f[k * H + tx], acc);
        d_Tf[z * H + tx] = acc;
    } else {
        int j = tx - 64;
#pragma unroll 8
        for (int k = 0; k < H; k++) acc = fmaf(e[k], w_c[k * H + j], acc);
        d_Tc[z * H + j] = acc;
    }
}

__global__ void k_gcnt(const int* __restrict__ batch) {
    int i = blockIdx.x * blockDim.x + threadIdx.x;
    if (i < NA) red_add_1(&d_gcnt[batch[i]], 1.0f);
}

// phase A: scatter emb[z[src]] into hx[hid] + incidence counts (fused)
__global__ __launch_bounds__(256) void k_scatter(const int* __restrict__ src,
                                                 const int* __restrict__ hid,
                                                 const int* __restrict__ az,
                                                 const float* __restrict__ emb) {
    __shared__ float T[NZ * H];
    for (int i = threadIdx.x; i < NZ * H; i += 256) T[i] = emb[i];
    __syncthreads();
    int stride = gridDim.x * 256;
    for (int idx = blockIdx.x * 256 + threadIdx.x; idx < NI * 16; idx += stride) {
        int e = idx >> 4;
        int q = (idx & 15) << 2;
        int s = __ldg(src + e);
        int m = __ldg(hid + e);
        int z = __ldg(az + s);
        float4 v = *reinterpret_cast<const float4*>(&T[z * H + q]);
        red_add_v4(d_hx + m * H + q, v);
        if ((idx & 15) == 0) {
            red_add_1(&d_cnt_s[s], 1.0f);
            red_add_1(&d_cnt_h[m], 1.0f);
        }
    }
}

// per-motif GEMM:  [Mf|Mc] = [hx_mean | attr] @ [w_f[64:] | w_c[64:]] + bias
// 64 rows x 128 cols per block; 256 threads; each thread: 8 rows x 4 cols
__global__ __launch_bounds__(256) void k_gemm_motifs(const float* __restrict__ w_f,
                                                     const float* __restrict__ w_c,
                                                     const float* __restrict__ b_f,
                                                     const float* __restrict__ b_c,
                                                     const float* __restrict__ attr) {
    extern __shared__ float smbuf[];
    float* Wsm = smbuf;              // ZK * 128
    float* Xsm = smbuf + ZK * 128;   // 64 * ZK
    int t = threadIdx.x;
    int tx = t & 31;                 // col group: cols tx*4 .. tx*4+3
    int ry = t >> 5;                 // row group: rows ry*8 .. ry*8+7

    for (int idx = t; idx < ZK * 128; idx += 256) {
        int k = idx >> 7, j = idx & 127;
        Wsm[idx] = (j < 64) ? w_f[(64 + k) * H + j] : w_c[(64 + k) * H + j - 64];
    }
    int row0 = blockIdx.x * 64;
    for (int idx = t; idx < 64 * ZK; idx += 256) {
        int r = idx / ZK;
        int k = idx - r * ZK;
        int row = row0 + r;
        float v = 0.f;
        if (row < NM) {
            if (k < 64) v = d_hx[row * H + k] * __fdividef(1.0f, fmaxf(d_cnt_h[row], 1.0f));
            else        v = attr[row * MD + (k - 64)];
        }
        Xsm[idx] = v;
    }
    __syncthreads();

    float acc[8][4];
#pragma unroll
    for (int r = 0; r < 8; r++)
#pragma unroll
        for (int c = 0; c < 4; c++) acc[r][c] = 0.f;

#pragma unroll 2
    for (int k = 0; k < ZK; k++) {
        float4 wv = *reinterpret_cast<const float4*>(&Wsm[k * 128 + tx * 4]);
#pragma unroll
        for (int r = 0; r < 8; r++) {
            float xv = Xsm[(ry * 8 + r) * ZK + k];
            acc[r][0] = fmaf(xv, wv.x, acc[r][0]);
            acc[r][1] = fmaf(xv, wv.y, acc[r][1]);
            acc[r][2] = fmaf(xv, wv.z, acc[r][2]);
            acc[r][3] = fmaf(xv, wv.w, acc[r][3]);
        }
    }

    int col = tx * 4;
    float4 bias;
    if (col < 64) bias = *reinterpret_cast<const float4*>(&b_f[col]);
    else          bias = *reinterpret_cast<const float4*>(&b_c[col - 64]);
#pragma unroll
    for (int r = 0; r < 8; r++) {
        int row = row0 + ry * 8 + r;
        if (row < NM) {
            float4 o;
            o.x = acc[r][0] + bias.x; o.y = acc[r][1] + bias.y;
            o.z = acc[r][2] + bias.z; o.w = acc[r][3] + bias.w;
            if (col < 64) *reinterpret_cast<float4*>(&d_Mf[row * H + col]) = o;
            else          *reinterpret_cast<float4*>(&d_Mc[row * H + col - 64]) = o;
        }
    }
}

// phase B: gated message + scatter (Af/Ac from smem tables keyed by atom type)
__global__ __launch_bounds__(512) void k_msg(const int* __restrict__ src,
                                             const int* __restrict__ hid,
                                             const int* __restrict__ az) {
    extern __shared__ float Tm[];    // [0:NZ*H) = Tf, [NZ*H:2*NZ*H) = Tc
    for (int i = threadIdx.x; i < NZ * H; i += 512) {
        Tm[i] = d_Tf[i];
        Tm[NZ * H + i] = d_Tc[i];
    }
    __syncthreads();
    int stride = gridDim.x * 512;
    for (int idx = blockIdx.x * 512 + threadIdx.x; idx < NI * 16; idx += stride) {
        int e = idx >> 4;
        int q = (idx & 15) << 2;
        int s = __ldg(src + e);
        int m = __ldg(hid + e);
        int z = __ldg(az + s);
        float4 af = *reinterpret_cast<const float4*>(&Tm[z * H + q]);
        float4 ac = *reinterpret_cast<const float4*>(&Tm[NZ * H + z * H + q]);
        float4 mf = *reinterpret_cast<const float4*>(d_Mf + m * H + q);
        float4 mc = *reinterpret_cast<const float4*>(d_Mc + m * H + q);
        float4 r;
        r.x = gatef(af.x + mf.x, ac.x + mc.x);
        r.y = gatef(af.y + mf.y, ac.y + mc.y);
        r.z = gatef(af.z + mf.z, ac.z + mc.z);
        r.w = gatef(af.w + mf.w, ac.w + mc.w);
        red_add_v4(d_osum + s * H + q, r);
    }
}

// BN statistics
__global__ void k_bnstats() {
    __shared__ float s1[256], s2[256];
    int t = threadIdx.x;
    float ls = 0.f, lq = 0.f;
    int stride = gridDim.x * blockDim.x;   // multiple of 64
    for (int i = blockIdx.x * blockDim.x + t; i < NA * H; i += stride) {
        int row = i >> 6;
        float o = d_osum[i] * __fdividef(1.0f, fmaxf(d_cnt_s[row], 1.0f));
        ls += o;
        lq += o * o;
    }
    s1[t] = ls; s2[t] = lq;
    __syncthreads();
    if (t < 64) {
        float a = s1[t] + s1[t + 64] + s1[t + 128] + s1[t + 192];
        float b = s2[t] + s2[t + 64] + s2[t + 128] + s2[t + 192];
        atomicAdd(&d_bnsum[t], a);
        atomicAdd(&d_bnsq[t], b);
    }
}

// normalize + residual + relu + pool into graphs
__global__ void k_final(const int* __restrict__ batch, const float* __restrict__ gamma,
                        const float* __restrict__ beta, const int* __restrict__ az,
                        const float* __restrict__ emb) {
    int tid = blockIdx.x * blockDim.x + threadIdx.x;
    if (tid >= NA * 16) return;
    int i = tid >> 4;
    int q = (tid & 15) << 2;
    float rc = __fdividef(1.0f, fmaxf(d_cnt_s[i], 1.0f));
    int z = __ldg(az + i);
    float4 o = *reinterpret_cast<const float4*>(d_osum + i * H + q);
    float4 xv = *reinterpret_cast<const float4*>(&emb[z * H + q]);
    float ov[4] = {o.x, o.y, o.z, o.w};
    float xr[4] = {xv.x, xv.y, xv.z, xv.w};
    float res[4];
#pragma unroll
    for (int c = 0; c < 4; c++) {
        int f = q + c;
        float mu = d_bnsum[f] * (1.0f / NA);
        float var = d_bnsq[f] * (1.0f / NA) - mu * mu;
        float inv = rsqrtf(var + BN_EPS);
        float v = (ov[c] * rc - mu) * inv * gamma[f] + beta[f] + xr[c];
        res[c] = fmaxf(v, 0.f);
    }
    float4 r; r.x = res[0]; r.y = res[1]; r.z = res[2]; r.w = res[3];
    int g = __ldg(batch + i);
    red_add_v4(d_gsum + g * H + q, r);
}

// MLP head
__global__ __launch_bounds__(128) void k_head(const float* __restrict__ w_l1,
                                              const float* __restrict__ b_l1,
                                              const float* __restrict__ w_out,
                                              const float* __restrict__ b_out,
                                              float* __restrict__ out) {
    __shared__ float gsm[64];
    __shared__ float red[128];
    int g = blockIdx.x;
    int t = threadIdx.x;
    if (t < 64) gsm[t] = d_gsum[g * H + t] * __fdividef(1.0f, fmaxf(d_gcnt[g], 1.0f));
    __syncthreads();
    float acc = b_l1[t];
#pragma unroll
    for (int f = 0; f < 64; f++)
        acc = fmaf(gsm[f], w_l1[f * HOUT + t], acc);
    float sp = lg2f(1.0f + ex2f(acc * L2E)) * LN2;
    red[t] = sp * w_out[t];
    __syncthreads();
    if (t < 64) red[t] += red[t + 64];
    __syncthreads();
    if (t < 32) {
        float s = red[t] + red[t + 32];
#pragma unroll
        for (int off = 16; off > 0; off >>= 1)
            s += __shfl_down_sync(0xffffffff, s, off);
        if (t == 0) out[g] = s + b_out[0];
    }
}

// ---------------- launch ----------------
extern "C" void kernel_launch(void* const* d_in, const int* in_sizes, int n_in,
                              void* d_out, int out_size) {
    const int*   atom_z = (const int*)d_in[0];
    const float* attr   = (const float*)d_in[1];
    const int*   hei    = (const int*)d_in[2];
    const int*   batch  = (const int*)d_in[3];
    const float* emb    = (const float*)d_in[4];
    const float* w_f    = (const float*)d_in[5];
    const float* b_f    = (const float*)d_in[6];
    const float* w_c    = (const float*)d_in[7];
    const float* b_c    = (const float*)d_in[8];
    const float* gamma  = (const float*)d_in[9];
    const float* beta   = (const float*)d_in[10];
    const float* w_l1   = (const float*)d_in[11];
    const float* b_l1   = (const float*)d_in[12];
    const float* w_out  = (const float*)d_in[13];
    const float* b_out  = (const float*)d_in[14];
    float* out = (float*)d_out;

    const int* src = hei;
    const int* hid = hei + NI;

    const int gemm_smem = (ZK * 128 + 64 * ZK) * (int)sizeof(float);  // 121344 B
    const int msg_smem  = 2 * NZ * H * (int)sizeof(float);            // 51712 B
    static int attr_done = 0;
    cudaFuncSetAttribute(k_gemm_motifs, cudaFuncAttributeMaxDynamicSharedMemorySize, gemm_smem);
    cudaFuncSetAttribute(k_msg, cudaFuncAttributeMaxDynamicSharedMemorySize, msg_smem);
    (void)attr_done;

    k_zero<<<1024, 256>>>();
    k_tables<<<NZ, 128>>>(emb, w_f, w_c);
    k_gcnt<<<(NA + 255) / 256, 256>>>(batch);
    k_scatter<<<1184, 256>>>(src, hid, atom_z, emb);
    k_gemm_motifs<<<(NM + 63) / 64, 256, gemm_smem>>>(w_f, w_c, b_f, b_c, attr);
    k_msg<<<592, 512, msg_smem>>>(src, hid, atom_z);
    k_bnstats<<<1024, 256>>>();
    k_final<<<(NA * 16 + 255) / 256, 256>>>(batch, gamma, beta, atom_z, emb);
    k_head<<<NG, 128>>>(w_l1, b_l1, w_out, b_out, out);
}